// round 16
// baseline (speedup 1.0000x reference)
#include <cuda_runtime.h>
#include <math.h>

// Problem constants
#define NM 100000
#define NS 20000
#define NT 200000
#define CC 64
#define EMT 1000000
#define EST 500000
#define MAXN NT

#define BM ((NM + 63) / 64)   // 1563
#define BS ((NS + 63) / 64)   // 313
#define BT ((NT + 63) / 64)   // 3125

// gather warp-segment bounds, TEAM SEGMENTS FIRST (e0, e2, then e1, e3)
#define WG0 (NT / 2)          // e0: dst team
#define WG2 (NT / 2)          // e2: dst team
#define WG1 (NM / 2)          // e1: dst member
#define WG3 (NS / 2)          // e3: dst skill
#define WGT (WG0 + WG2)                 // 200000 team-dst warps
#define WGMS (WG1 + WG3)                // 60000 member/skill-dst warps
#define GT_BLOCKS ((WGT * 32 + 255) / 256)    // 25000
#define GMS_BLOCKS ((WGMS * 32 + 255) / 256)  // 7500

#define ETOT (2 * EMT + 2 * EST)        // 3,000,000

// scan segment bounds
#define SCAN_BLOCK 1024
#define SCAN_ITEMS 2048
#define NSC0 (NT + 1)
#define NSC1 (NM + 1)
#define NSC2 (NT + 1)
#define NSC3 (NS + 1)
#define NB0 ((NSC0 + SCAN_ITEMS - 1) / SCAN_ITEMS)
#define NB1 ((NSC1 + SCAN_ITEMS - 1) / SCAN_ITEMS)
#define NB2 ((NSC2 + SCAN_ITEMS - 1) / SCAN_ITEMS)
#define NB3 ((NSC3 + SCAN_ITEMS - 1) / SCAN_ITEMS)
#define NBTOT (NB0 + NB1 + NB2 + NB3)
#define NSCTOT (NSC0 + NSC1 + NSC2 + NSC3)

// ---------------- static device scratch ----------------
__device__ float g_h0[NM * CC];
__device__ float g_h1[NS * CC];
__device__ float g_h2[NT * CC];
__device__ float g_o0[NM * CC];
__device__ float g_o1[NS * CC];
__device__ float g_oT0[NT * CC];
__device__ float g_oT1[NT * CC];
__device__ float g_as[4][MAXN * 2];
__device__ float g_ad[4][MAXN * 2];
__device__ float g_acc[2 * CC];
__device__ float g_w[2];

// CSR scratch
__device__ int g_cnt[4][MAXN + 1];
__device__ int g_off[4][MAXN + 1];
__device__ int g_fill[4][MAXN + 1];
__device__ int g_ssrc[ETOT];
__device__ int g_bsum[4][128];

__device__ __forceinline__ float fast_tanh(float x) {
    float y;
    asm("tanh.approx.f32 %0, %1;" : "=f"(y) : "f"(x));
    return y;
}

// ---------------- merged CSR build kernels ----------------
__global__ void hist4_kernel(const int* __restrict__ d0, const int* __restrict__ d1,
                             const int* __restrict__ d2, const int* __restrict__ d3)
{
    int i = blockIdx.x * blockDim.x + threadIdx.x;
    if (i < EMT)                   atomicAdd(&g_cnt[0][d0[i]], 1);
    else if (i < 2 * EMT)          atomicAdd(&g_cnt[1][d1[i - EMT]], 1);
    else if (i < 2 * EMT + EST)    atomicAdd(&g_cnt[2][d2[i - 2 * EMT]], 1);
    else if (i < ETOT)             atomicAdd(&g_cnt[3][d3[i - 2 * EMT - EST]], 1);
}

__global__ __launch_bounds__(SCAN_BLOCK) void scan1m_kernel()
{
    __shared__ int wsum[32];
    int b = blockIdx.x;
    int e, blk, n;
    if (b < NB0)                  { e = 0; blk = b;               n = NSC0; }
    else if (b < NB0 + NB1)       { e = 1; blk = b - NB0;         n = NSC1; }
    else if (b < NB0 + NB1 + NB2) { e = 2; blk = b - NB0 - NB1;   n = NSC2; }
    else                          { e = 3; blk = b - NB0 - NB1 - NB2; n = NSC3; }
    const int* cnt = &g_cnt[e][0];
    int* off = &g_off[e][0];
    int* bsum = &g_bsum[e][0];

    int t = threadIdx.x;
    long base = (long)blk * SCAN_ITEMS;
    long i0 = base + 2 * t, i1 = i0 + 1;
    int a0 = (i0 < n) ? cnt[i0] : 0;
    int a1 = (i1 < n) ? cnt[i1] : 0;
    int ts = a0 + a1;
    int lane = t & 31, w = t >> 5;
    int v = ts;
    #pragma unroll
    for (int o = 1; o < 32; o <<= 1) { int u = __shfl_up_sync(~0u, v, o); if (lane >= o) v += u; }
    if (lane == 31) wsum[w] = v;
    __syncthreads();
    if (w == 0) {
        int x = wsum[lane];
        #pragma unroll
        for (int o = 1; o < 32; o <<= 1) { int u = __shfl_up_sync(~0u, x, o); if (lane >= o) x += u; }
        wsum[lane] = x;
    }
    __syncthreads();
    int warp_prefix = (w == 0) ? 0 : wsum[w - 1];
    int excl = warp_prefix + (v - ts);
    if (i0 < n) off[i0] = excl;
    if (i1 < n) off[i1] = excl + a0;
    if (t == 0) bsum[blk] = wsum[31];
}

__global__ void scan2m_kernel()
{
    __shared__ int ws[4];
    int e = blockIdx.x;
    const int nbs[4] = {NB0, NB1, NB2, NB3};
    int nb = nbs[e];
    int* bsum = &g_bsum[e][0];
    int t = threadIdx.x;
    int v = (t < nb) ? bsum[t] : 0;
    int lane = t & 31, w = t >> 5;
    int x = v;
    #pragma unroll
    for (int o = 1; o < 32; o <<= 1) { int u = __shfl_up_sync(~0u, x, o); if (lane >= o) x += u; }
    if (lane == 31) ws[w] = x;
    __syncthreads();
    if (t == 0) { int s = 0; for (int i = 0; i < 4; i++) { int c = ws[i]; ws[i] = s; s += c; } }
    __syncthreads();
    int excl = ws[w] + (x - v);
    if (t < nb) bsum[t] = excl;
}

__global__ void scan3m_kernel()
{
    long i = (long)blockIdx.x * blockDim.x + threadIdx.x;
    int e; long li;
    if (i < NSC0)                        { e = 0; li = i; }
    else if (i < NSC0 + NSC1)            { e = 1; li = i - NSC0; }
    else if (i < NSC0 + NSC1 + NSC2)     { e = 2; li = i - NSC0 - NSC1; }
    else if (i < NSCTOT)                 { e = 3; li = i - NSC0 - NSC1 - NSC2; }
    else return;
    g_off[e][li] += g_bsum[e][li / SCAN_ITEMS];
}

__global__ void scatter4_kernel(
    const int* __restrict__ d0, const int* __restrict__ s0,
    const int* __restrict__ d1, const int* __restrict__ s1,
    const int* __restrict__ d2, const int* __restrict__ s2,
    const int* __restrict__ d3, const int* __restrict__ s3)
{
    int i = blockIdx.x * blockDim.x + threadIdx.x;
    int e; int li;
    const int* dst; const int* src; int base;
    if (i < EMT)                { e = 0; li = i;                 dst = d0; src = s0; base = 0; }
    else if (i < 2 * EMT)       { e = 1; li = i - EMT;           dst = d1; src = s1; base = EMT; }
    else if (i < 2 * EMT + EST) { e = 2; li = i - 2 * EMT;       dst = d2; src = s2; base = 2 * EMT; }
    else if (i < ETOT)          { e = 3; li = i - 2 * EMT - EST; dst = d3; src = s3; base = 2 * EMT + EST; }
    else return;
    int pos = atomicAdd(&g_fill[e][dst[li]], 1);
    g_ssrc[base + pos] = src[li];
}

// ================= GEMM body (shared by proj/lin variants) =================
#define GEMM_BODY(XA, XB, NROWS)                                               \
    int t = threadIdx.x;                                                       \
    for (int i = t; i < 4096; i += 256) {                                      \
        int k = i >> 6, c = i & 63; sWt[c * 68 + k] = W[i];                    \
    }                                                                          \
    __syncthreads();                                                           \
    int lane = t & 31, slot = t >> 5;                                          \
    long r0 = rblk + slot * 8;                                                 \
    float w0 = 1.f, w1 = 0.f;                                                  \
    if (XB) { w0 = g_w[0]; w1 = g_w[1]; }                                      \
    for (int j = lane; j < 128; j += 32) {                                     \
        int r = j >> 4, kk = (j & 15) * 4;                                     \
        float4 vv = make_float4(0.f, 0.f, 0.f, 0.f);                           \
        if (r0 + r < NROWS) {                                                  \
            vv = *(const float4*)(XA + (r0 + r) * 64 + kk);                    \
            if (XB) {                                                          \
                float4 vb = *(const float4*)(XB + (r0 + r) * 64 + kk);         \
                vv.x = w0 * vv.x + w1 * vb.x;                                  \
                vv.y = w0 * vv.y + w1 * vb.y;                                  \
                vv.z = w0 * vv.z + w1 * vb.z;                                  \
                vv.w = w0 * vv.w + w1 * vb.w;                                  \
            }                                                                  \
        }                                                                      \
        *(float4*)&sX[slot][r * 64 + kk] = vv;                                 \
    }                                                                          \
    __syncwarp();                                                              \
    float b0 = bias[lane], b1 = bias[lane + 32];                               \
    float acc0[8], acc1[8];                                                    \
    _Pragma("unroll")                                                          \
    for (int r = 0; r < 8; r++) { acc0[r] = b0; acc1[r] = b1; }                \
    _Pragma("unroll")                                                          \
    for (int k = 0; k < 64; k += 4) {                                          \
        float4 wv0 = *(const float4*)&sWt[lane * 68 + k];                      \
        float4 wv1 = *(const float4*)&sWt[(lane + 32) * 68 + k];               \
        _Pragma("unroll")                                                      \
        for (int r = 0; r < 8; r++) {                                          \
            float4 xv = *(const float4*)&sX[slot][r * 64 + k];                 \
            acc0[r] += xv.x * wv0.x + xv.y * wv0.y + xv.z * wv0.z + xv.w * wv0.w; \
            acc1[r] += xv.x * wv1.x + xv.y * wv1.y + xv.z * wv1.z + xv.w * wv1.w; \
        }                                                                      \
    }

#define ATT_DOTS(NROWS)                                                        \
    _Pragma("unroll")                                                          \
    for (int v = 0; v < 2; v++) {                                              \
        float a0v = sAv[v * 64 + lane], a1v = sAv[v * 64 + lane + 32];         \
        _Pragma("unroll")                                                      \
        for (int r = 0; r < 8; r++) {                                          \
            float p0 = acc0[r] * a0v;                                          \
            float p1 = acc1[r] * a1v;                                          \
            _Pragma("unroll")                                                  \
            for (int off = 16; off; off >>= 1) {                               \
                p0 += __shfl_xor_sync(0xffffffffu, p0, off);                   \
                p1 += __shfl_xor_sync(0xffffffffu, p1, off);                   \
            }                                                                  \
            if (lane == 0 && r0 + r < NROWS) {                                 \
                aop[v][(r0 + r) * 2]     = p0;                                 \
                aop[v][(r0 + r) * 2 + 1] = p1;                                 \
            }                                                                  \
        }                                                                      \
    }

// ---------------- member+skill projection ----------------
__global__ __launch_bounds__(256) void proj_ms_kernel(
    const float* __restrict__ xm, const float* __restrict__ xs,
    const float* __restrict__ Wb, const float* __restrict__ bb,
    const float* __restrict__ aSb, const float* __restrict__ aDb)
{
    __shared__ float sWt[64 * 68];
    __shared__ float sAv[2 * 64];
    __shared__ float sX[8][512];

    int b = blockIdx.x;
    int N; long rblk;
    const float* xA;
    float* hout;
    const float* avp[2];
    float* aop[2];
    const float* W; const float* bias;

    if (b < BM) {
        N = NM; rblk = (long)b * 64; xA = xm; hout = g_h0;
        avp[0] = aSb + 0;   aop[0] = &g_as[0][0];
        avp[1] = aDb + 64;  aop[1] = &g_ad[1][0];
        W = Wb; bias = bb;
    } else {
        N = NS; rblk = (long)(b - BM) * 64; xA = xs; hout = g_h1;
        avp[0] = aSb + 128; aop[0] = &g_as[2][0];
        avp[1] = aDb + 192; aop[1] = &g_ad[3][0];
        W = Wb + 4096; bias = bb + 64;
    }
    if (threadIdx.x < 64) {
        sAv[threadIdx.x] = avp[0][threadIdx.x];
        sAv[64 + threadIdx.x] = avp[1][threadIdx.x];
    }

    const float* xB = nullptr;
    GEMM_BODY(xA, xB, N)

    #pragma unroll
    for (int r = 0; r < 8; r++) {
        if (r0 + r < N) {
            hout[(r0 + r) * 64 + lane]      = acc0[r];
            hout[(r0 + r) * 64 + lane + 32] = acc1[r];
        }
    }
    ATT_DOTS(N)
}

// ---------------- team projection (with semantic blend) ----------------
__global__ __launch_bounds__(256) void proj_t_kernel(
    const float* __restrict__ xtA, const float* __restrict__ xtB,
    const float* __restrict__ Wb, const float* __restrict__ bb,
    const float* __restrict__ aSb, const float* __restrict__ aDb)
{
    __shared__ float sWt[64 * 68];
    __shared__ float sAv[4 * 64];
    __shared__ float sX[8][512];

    long rblk = (long)blockIdx.x * 64;
    const float* W = Wb + 2 * 4096;
    const float* bias = bb + 2 * 64;
    const float* avp[4] = {aSb + 64, aSb + 192, aDb + 0, aDb + 128};
    float* aop[4] = {&g_as[1][0], &g_as[3][0], &g_ad[0][0], &g_ad[2][0]};
    if (threadIdx.x < 64) {
        #pragma unroll
        for (int v = 0; v < 4; v++) sAv[v * 64 + threadIdx.x] = avp[v][threadIdx.x];
    }

    GEMM_BODY(xtA, xtB, NT)

    #pragma unroll
    for (int r = 0; r < 8; r++) {
        if (r0 + r < NT) {
            g_h2[(r0 + r) * 64 + lane]      = acc0[r];
            g_h2[(r0 + r) * 64 + lane + 32] = acc1[r];
        }
    }

    #pragma unroll
    for (int v = 0; v < 4; v++) {
        float a0v = sAv[v * 64 + lane], a1v = sAv[v * 64 + lane + 32];
        #pragma unroll
        for (int r = 0; r < 8; r++) {
            float p0 = acc0[r] * a0v;
            float p1 = acc1[r] * a1v;
            #pragma unroll
            for (int off = 16; off; off >>= 1) {
                p0 += __shfl_xor_sync(0xffffffffu, p0, off);
                p1 += __shfl_xor_sync(0xffffffffu, p1, off);
            }
            if (lane == 0 && r0 + r < NT) {
                aop[v][(r0 + r) * 2]     = p0;
                aop[v][(r0 + r) * 2 + 1] = p1;
            }
        }
    }
}

// ---------------- gather segment kernel (MLP-2 inner loop) ----------------
// Segment layout (warp units): [0,WG0): e0 | [WG0,WG0+WG2): e2 |
//   [WGT, WGT+WG1): e1 | [WGT+WG1, WGT+WGMS): e3
__global__ __launch_bounds__(256) void gather_seg_kernel(long gwbase)
{
    long gw = gwbase + (((long)blockIdx.x * blockDim.x + threadIdx.x) >> 5);
    int lane = threadIdx.x & 31;
    int li = lane & 15;
    int hb = lane & 16;

    int e; long lw;
    if (gw < WG0)                 { e = 0; lw = gw; }
    else if (gw < WGT)            { e = 2; lw = gw - WG0; }
    else if (gw < WGT + WG1)      { e = 1; lw = gw - WGT; }
    else if (gw < WGT + WGMS)     { e = 3; lw = gw - WGT - WG1; }
    else return;

    const float* h;
    float* outp;
    const int* ssrc;
    int N;
    if (e == 0)      { h = g_h0; outp = g_oT0; ssrc = g_ssrc;                 N = NT; }
    else if (e == 1) { h = g_h2; outp = g_o0;  ssrc = g_ssrc + EMT;           N = NM; }
    else if (e == 2) { h = g_h1; outp = g_oT1; ssrc = g_ssrc + 2 * EMT;       N = NT; }
    else             { h = g_h2; outp = g_o1;  ssrc = g_ssrc + 2 * EMT + EST; N = NS; }
    const float* as = &g_as[e][0];
    const float* ad = &g_ad[e][0];
    const int* off = &g_off[e][0];

    long d = lw * 2 + (hb >> 4);
    bool act = d < N;
    int beg = 0, end = 0;
    if (act) { beg = off[d]; end = off[d + 1]; }
    int head = li >> 3;

    float ad0 = 0.f, ad1 = 0.f;
    if (act) { float2 tt = *(const float2*)(ad + d * 2); ad0 = tt.x; ad1 = tt.y; }

    float4 accA = make_float4(0.f, 0.f, 0.f, 0.f);
    float4 accB = make_float4(0.f, 0.f, 0.f, 0.f);
    float se0 = 0.f, se1 = 0.f;

    int trips = (end - beg + 15) >> 4;
    trips = max(trips, __shfl_xor_sync(0xffffffffu, trips, 16));

    for (int k = 0; k < trips; k++) {
        int base = beg + (k << 4);
        int idx = base + li;
        int s = 0;
        float ex0 = 0.f, ex1 = 0.f;
        if (idx < end) {
            s = ssrc[idx];
            float2 av = *(const float2*)(as + (long)s * 2);
            float l0 = av.x + ad0; l0 = (l0 >= 0.f) ? l0 : 0.2f * l0;
            float l1 = av.y + ad1; l1 = (l1 >= 0.f) ? l1 : 0.2f * l1;
            ex0 = __expf(l0); ex1 = __expf(l1);
            se0 += ex0; se1 += ex1;
        }
        int cnt = end - base;
        cnt = (cnt < 0) ? 0 : ((cnt > 16) ? 16 : cnt);
        int cntmax = max(cnt, __shfl_xor_sync(0xffffffffu, cnt, 16));
        int i = 0;
        // unrolled-by-2: both loads issued before their FMA chains -> MLP ~2
        for (; i + 2 <= cntmax; i += 2) {
            int sl0 = hb + i, sl1 = hb + i + 1;
            int si0   = __shfl_sync(0xffffffffu, s,   sl0);
            int si1   = __shfl_sync(0xffffffffu, s,   sl1);
            float a00 = __shfl_sync(0xffffffffu, ex0, sl0);
            float a01 = __shfl_sync(0xffffffffu, ex1, sl0);
            float a10 = __shfl_sync(0xffffffffu, ex0, sl1);
            float a11 = __shfl_sync(0xffffffffu, ex1, sl1);
            const float4* p0 = (const float4*)(h + (long)si0 * 64 + li * 4);
            const float4* p1 = (const float4*)(h + (long)si1 * 64 + li * 4);
            float4 v0 = *p0;
            float4 v1 = *p1;
            float ee0 = head ? a01 : a00;
            float ee1 = head ? a11 : a10;
            accA.x += ee0 * v0.x; accA.y += ee0 * v0.y;
            accA.z += ee0 * v0.z; accA.w += ee0 * v0.w;
            accB.x += ee1 * v1.x; accB.y += ee1 * v1.y;
            accB.z += ee1 * v1.z; accB.w += ee1 * v1.w;
        }
        for (; i < cntmax; i++) {
            int sl = hb + i;
            int si   = __shfl_sync(0xffffffffu, s,   sl);
            float e0 = __shfl_sync(0xffffffffu, ex0, sl);
            float e1 = __shfl_sync(0xffffffffu, ex1, sl);
            float ee = head ? e1 : e0;
            float4 hv = *(const float4*)(h + (long)si * 64 + li * 4);
            accA.x += ee * hv.x;
            accA.y += ee * hv.y;
            accA.z += ee * hv.z;
            accA.w += ee * hv.w;
        }
    }

    float4 acc;
    acc.x = accA.x + accB.x;
    acc.y = accA.y + accB.y;
    acc.z = accA.z + accB.z;
    acc.w = accA.w + accB.w;

    #pragma unroll
    for (int o = 8; o; o >>= 1) {
        se0 += __shfl_xor_sync(0xffffffffu, se0, o);
        se1 += __shfl_xor_sync(0xffffffffu, se1, o);
    }
    if (act) {
        float inv = 1.0f / ((head ? se1 : se0) + 1e-16f);
        acc.x = fmaxf(acc.x * inv, 0.f);
        acc.y = fmaxf(acc.y * inv, 0.f);
        acc.z = fmaxf(acc.z * inv, 0.f);
        acc.w = fmaxf(acc.w * inv, 0.f);
        *(float4*)(outp + d * 64 + li * 4) = acc;
    }
}

// ---------------- merged semantic GEMM reduction ----------------
__global__ __launch_bounds__(256) void sem2_kernel(
    const float* __restrict__ W, const float* __restrict__ bias)
{
    __shared__ float sWt[64 * 68];
    __shared__ float sX[8][512];
    __shared__ float sAcc[64];

    int b = blockIdx.x;
    const float* xA = (b < BT) ? g_oT0 : g_oT1;
    float* acc_out = (b < BT) ? g_acc : (g_acc + 64);
    long rblk = (long)((b < BT) ? b : (b - BT)) * 64;
    if (threadIdx.x < 64) sAcc[threadIdx.x] = 0.f;

    const float* xB = nullptr;
    GEMM_BODY(xA, xB, NT)

    float s0 = 0.f, s1 = 0.f;
    #pragma unroll
    for (int r = 0; r < 8; r++) {
        if (r0 + r < NT) { s0 += fast_tanh(acc0[r]); s1 += fast_tanh(acc1[r]); }
    }
    atomicAdd(&sAcc[lane], s0);
    atomicAdd(&sAcc[lane + 32], s1);
    __syncthreads();
    if (t < 64) atomicAdd(&acc_out[t], sAcc[t]);
}

// ---------------- semantic finalize (re-zeros acc) ----------------
__global__ void sem_finalize_kernel(const float* __restrict__ q)
{
    __shared__ float s0[64], s1[64];
    int t = threadIdx.x;
    s0[t] = q[t] * g_acc[t]      * (1.0f / NT);
    s1[t] = q[t] * g_acc[64 + t] * (1.0f / NT);
    __syncthreads();
    g_acc[t] = 0.f;
    g_acc[64 + t] = 0.f;
    if (t == 0) {
        float a = 0.f, b = 0.f;
        for (int i = 0; i < 64; i++) { a += s0[i]; b += s1[i]; }
        float m = fmaxf(a, b);
        float e0 = __expf(a - m), e1 = __expf(b - m);
        float inv = 1.0f / (e0 + e1);
        g_w[0] = e0 * inv;
        g_w[1] = e1 * inv;
    }
}

// ---------------- final linear: member+skill ----------------
__global__ __launch_bounds__(256) void lin_ms_kernel(
    const float* __restrict__ W, const float* __restrict__ bias, float* __restrict__ out)
{
    __shared__ float sWt[64 * 68];
    __shared__ float sX[8][512];

    int b = blockIdx.x;
    int N; long rblk;
    const float* xA;
    float* op;
    if (b < BM) { N = NM; rblk = (long)b * 64; xA = g_o0; op = out; }
    else        { N = NS; rblk = (long)(b - BM) * 64; xA = g_o1; op = out + (long)NM * 64; }

    const float* xB = nullptr;
    GEMM_BODY(xA, xB, N)

    #pragma unroll
    for (int r = 0; r < 8; r++) {
        if (r0 + r < N) {
            op[(r0 + r) * 64 + lane]      = acc0[r];
            op[(r0 + r) * 64 + lane + 32] = acc1[r];
        }
    }
}

// ---------------- final linear: team (with blend) ----------------
__global__ __launch_bounds__(256) void lin_t_kernel(
    const float* __restrict__ W, const float* __restrict__ bias, float* __restrict__ out)
{
    __shared__ float sWt[64 * 68];
    __shared__ float sX[8][512];

    long rblk = (long)blockIdx.x * 64;
    float* op = out + (long)(NM + NS) * 64;

    GEMM_BODY(g_oT0, g_oT1, NT)

    #pragma unroll
    for (int r = 0; r < 8; r++) {
        if (r0 + r < NT) {
            op[(r0 + r) * 64 + lane]      = acc0[r];
            op[(r0 + r) * 64 + lane + 32] = acc1[r];
        }
    }
}

// ---------------- host orchestration ----------------
extern "C" void kernel_launch(void* const* d_in, const int* in_sizes, int n_in,
                              void* d_out, int out_size)
{
    (void)in_sizes; (void)n_in; (void)out_size;
    const float* x_m  = (const float*)d_in[0];
    const float* x_s  = (const float*)d_in[1];
    const float* x_t  = (const float*)d_in[2];
    const int* src_mt = (const int*)d_in[3];
    const int* dst_mt = (const int*)d_in[4];
    const int* src_tm = (const int*)d_in[5];
    const int* dst_tm = (const int*)d_in[6];
    const int* src_st = (const int*)d_in[7];
    const int* dst_st = (const int*)d_in[8];
    const int* src_ts = (const int*)d_in[9];
    const int* dst_ts = (const int*)d_in[10];
    const float* Wp   = (const float*)d_in[11];
    const float* bp   = (const float*)d_in[12];
    const float* aS   = (const float*)d_in[13];
    const float* aD   = (const float*)d_in[14];
    const float* kWp  = (const float*)d_in[15];
    const float* kbp  = (const float*)d_in[16];
    const float* qp   = (const float*)d_in[17];
    const float* linW = (const float*)d_in[18];
    const float* linb = (const float*)d_in[19];
    float* out = (float*)d_out;

    float *o0, *o1, *oT0, *oT1, *accp;
    int *cntb, *offb, *fillb;
    cudaGetSymbolAddress((void**)&o0,  g_o0);
    cudaGetSymbolAddress((void**)&o1,  g_o1);
    cudaGetSymbolAddress((void**)&oT0, g_oT0);
    cudaGetSymbolAddress((void**)&oT1, g_oT1);
    cudaGetSymbolAddress((void**)&accp, g_acc);
    cudaGetSymbolAddress((void**)&cntb, g_cnt);
    cudaGetSymbolAddress((void**)&offb, g_off);
    cudaGetSymbolAddress((void**)&fillb, g_fill);

    static cudaStream_t s_side = nullptr;
    static cudaEvent_t s_fork = nullptr, s_join = nullptr, s_evG = nullptr, s_evS = nullptr;
    if (!s_side) {
        cudaStreamCreateWithFlags(&s_side, cudaStreamNonBlocking);
        cudaEventCreateWithFlags(&s_fork, cudaEventDisableTiming);
        cudaEventCreateWithFlags(&s_join, cudaEventDisableTiming);
        cudaEventCreateWithFlags(&s_evG, cudaEventDisableTiming);
        cudaEventCreateWithFlags(&s_evS, cudaEventDisableTiming);
    }

    // ---- fork: CSR build on side stream, overlapped with layer-0 projection ----
    cudaEventRecord(s_fork, 0);
    cudaStreamWaitEvent(s_side, s_fork, 0);

    cudaMemsetAsync(cntb, 0, sizeof(int) * 4 * (MAXN + 1), s_side);
    hist4_kernel<<<(ETOT + 255) / 256, 256, 0, s_side>>>(dst_mt, dst_tm, dst_st, dst_ts);
    scan1m_kernel<<<NBTOT, SCAN_BLOCK, 0, s_side>>>();
    scan2m_kernel<<<4, 128, 0, s_side>>>();
    scan3m_kernel<<<(NSCTOT + 255) / 256, 256, 0, s_side>>>();
    cudaMemcpyAsync(fillb, offb, sizeof(int) * 4 * (MAXN + 1),
                    cudaMemcpyDeviceToDevice, s_side);
    scatter4_kernel<<<(ETOT + 255) / 256, 256, 0, s_side>>>(
        dst_mt, src_mt, dst_tm, src_tm, dst_st, src_st, dst_ts, src_ts);
    cudaMemsetAsync(accp, 0, 128 * sizeof(float), s_side);
    cudaEventRecord(s_join, s_side);

    // layer-0 projection on main (no CSR, no g_w dependency)
    proj_ms_kernel<<<BM + BS, 256>>>(x_m, x_s, Wp, bp, aS, aD);
    proj_t_kernel<<<BT, 256>>>(x_t, nullptr, Wp, bp, aS, aD);

    cudaStreamWaitEvent(0, s_join, 0);

    for (int l = 0; l < 3; l++) {
        // team-destination gather first (produces oT0/oT1 for sem2)
        gather_seg_kernel<<<GT_BLOCKS, 256>>>(0);

        // fork: sem2 + finalize on side stream as soon as team gather is done
        cudaEventRecord(s_evG, 0);
        cudaStreamWaitEvent(s_side, s_evG, 0);
        sem2_kernel<<<2 * BT, 256, 0, s_side>>>(kWp + (long)l * 4096, kbp + (long)l * 64);
        sem_finalize_kernel<<<1, 64, 0, s_side>>>(qp + (long)l * 64);
        cudaEventRecord(s_evS, s_side);

        // member/skill-destination gather on main (independent of sem2)
        gather_seg_kernel<<<GMS_BLOCKS, 256>>>(WGT);

        // member/skill GEMM work on main (independent of g_w)
        if (l < 2) {
            proj_ms_kernel<<<BM + BS, 256>>>(o0, o1,
                Wp + (long)(l + 1) * 3 * 4096, bp + (long)(l + 1) * 3 * 64,
                aS + (long)(l + 1) * 4 * 64, aD + (long)(l + 1) * 4 * 64);
        } else {
            lin_ms_kernel<<<BM + BS, 256>>>(linW, linb, out);
        }

        // join, then team work (needs g_w)
        cudaStreamWaitEvent(0, s_evS, 0);
        if (l < 2) {
            proj_t_kernel<<<BT, 256>>>(oT0, oT1,
                Wp + (long)(l + 1) * 3 * 4096, bp + (long)(l + 1) * 3 * 64,
                aS + (long)(l + 1) * 4 * 64, aD + (long)(l + 1) * 4 * 64);
        } else {
            lin_t_kernel<<<BT, 256>>>(linW, linb, out);
        }
    }
}

// round 17
// speedup vs baseline: 1.1182x; 1.1182x over previous
#include <cuda_runtime.h>
#include <math.h>

// Problem constants
#define NM 100000
#define NS 20000
#define NT 200000
#define CC 64
#define EMT 1000000
#define EST 500000
#define MAXN NT

#define BM ((NM + 63) / 64)   // 1563
#define BS ((NS + 63) / 64)   // 313
#define BT ((NT + 63) / 64)   // 3125

// gather warp-segment bounds, TEAM SEGMENTS FIRST (e0, e2, then e1, e3)
// quarter-warp per destination => ceil(N/4) warps per type
#define WG0 (NT / 4)          // e0: dst team   50000
#define WG2 (NT / 4)          // e2: dst team   50000
#define WG1 (NM / 4)          // e1: dst member 25000
#define WG3 (NS / 4)          // e3: dst skill   5000
#define WGT (WG0 + WG2)                 // 100000 team-dst warps
#define WGMS (WG1 + WG3)                // 30000 member/skill-dst warps
#define GT_BLOCKS ((WGT * 32 + 255) / 256)    // 12500
#define GMS_BLOCKS ((WGMS * 32 + 255) / 256)  // 3750

#define ETOT (2 * EMT + 2 * EST)        // 3,000,000

// scan segment bounds
#define SCAN_BLOCK 1024
#define SCAN_ITEMS 2048
#define NSC0 (NT + 1)
#define NSC1 (NM + 1)
#define NSC2 (NT + 1)
#define NSC3 (NS + 1)
#define NB0 ((NSC0 + SCAN_ITEMS - 1) / SCAN_ITEMS)
#define NB1 ((NSC1 + SCAN_ITEMS - 1) / SCAN_ITEMS)
#define NB2 ((NSC2 + SCAN_ITEMS - 1) / SCAN_ITEMS)
#define NB3 ((NSC3 + SCAN_ITEMS - 1) / SCAN_ITEMS)
#define NBTOT (NB0 + NB1 + NB2 + NB3)
#define NSCTOT (NSC0 + NSC1 + NSC2 + NSC3)

// ---------------- static device scratch ----------------
__device__ float g_h0[NM * CC];
__device__ float g_h1[NS * CC];
__device__ float g_h2[NT * CC];
__device__ float g_o0[NM * CC];
__device__ float g_o1[NS * CC];
__device__ float g_oT0[NT * CC];
__device__ float g_oT1[NT * CC];
__device__ float g_as[4][MAXN * 2];
__device__ float g_ad[4][MAXN * 2];
__device__ float g_acc[2 * CC];
__device__ float g_w[2];

// CSR scratch
__device__ int g_cnt[4][MAXN + 1];
__device__ int g_off[4][MAXN + 1];
__device__ int g_fill[4][MAXN + 1];
__device__ int g_ssrc[ETOT];
__device__ int g_bsum[4][128];

__device__ __forceinline__ float fast_tanh(float x) {
    float y;
    asm("tanh.approx.f32 %0, %1;" : "=f"(y) : "f"(x));
    return y;
}

// ---------------- merged CSR build kernels ----------------
__global__ void hist4_kernel(const int* __restrict__ d0, const int* __restrict__ d1,
                             const int* __restrict__ d2, const int* __restrict__ d3)
{
    int i = blockIdx.x * blockDim.x + threadIdx.x;
    if (i < EMT)                   atomicAdd(&g_cnt[0][d0[i]], 1);
    else if (i < 2 * EMT)          atomicAdd(&g_cnt[1][d1[i - EMT]], 1);
    else if (i < 2 * EMT + EST)    atomicAdd(&g_cnt[2][d2[i - 2 * EMT]], 1);
    else if (i < ETOT)             atomicAdd(&g_cnt[3][d3[i - 2 * EMT - EST]], 1);
}

__global__ __launch_bounds__(SCAN_BLOCK) void scan1m_kernel()
{
    __shared__ int wsum[32];
    int b = blockIdx.x;
    int e, blk, n;
    if (b < NB0)                  { e = 0; blk = b;               n = NSC0; }
    else if (b < NB0 + NB1)       { e = 1; blk = b - NB0;         n = NSC1; }
    else if (b < NB0 + NB1 + NB2) { e = 2; blk = b - NB0 - NB1;   n = NSC2; }
    else                          { e = 3; blk = b - NB0 - NB1 - NB2; n = NSC3; }
    const int* cnt = &g_cnt[e][0];
    int* off = &g_off[e][0];
    int* bsum = &g_bsum[e][0];

    int t = threadIdx.x;
    long base = (long)blk * SCAN_ITEMS;
    long i0 = base + 2 * t, i1 = i0 + 1;
    int a0 = (i0 < n) ? cnt[i0] : 0;
    int a1 = (i1 < n) ? cnt[i1] : 0;
    int ts = a0 + a1;
    int lane = t & 31, w = t >> 5;
    int v = ts;
    #pragma unroll
    for (int o = 1; o < 32; o <<= 1) { int u = __shfl_up_sync(~0u, v, o); if (lane >= o) v += u; }
    if (lane == 31) wsum[w] = v;
    __syncthreads();
    if (w == 0) {
        int x = wsum[lane];
        #pragma unroll
        for (int o = 1; o < 32; o <<= 1) { int u = __shfl_up_sync(~0u, x, o); if (lane >= o) x += u; }
        wsum[lane] = x;
    }
    __syncthreads();
    int warp_prefix = (w == 0) ? 0 : wsum[w - 1];
    int excl = warp_prefix + (v - ts);
    if (i0 < n) off[i0] = excl;
    if (i1 < n) off[i1] = excl + a0;
    if (t == 0) bsum[blk] = wsum[31];
}

__global__ void scan2m_kernel()
{
    __shared__ int ws[4];
    int e = blockIdx.x;
    const int nbs[4] = {NB0, NB1, NB2, NB3};
    int nb = nbs[e];
    int* bsum = &g_bsum[e][0];
    int t = threadIdx.x;
    int v = (t < nb) ? bsum[t] : 0;
    int lane = t & 31, w = t >> 5;
    int x = v;
    #pragma unroll
    for (int o = 1; o < 32; o <<= 1) { int u = __shfl_up_sync(~0u, x, o); if (lane >= o) x += u; }
    if (lane == 31) ws[w] = x;
    __syncthreads();
    if (t == 0) { int s = 0; for (int i = 0; i < 4; i++) { int c = ws[i]; ws[i] = s; s += c; } }
    __syncthreads();
    int excl = ws[w] + (x - v);
    if (t < nb) bsum[t] = excl;
}

__global__ void scan3m_kernel()
{
    long i = (long)blockIdx.x * blockDim.x + threadIdx.x;
    int e; long li;
    if (i < NSC0)                        { e = 0; li = i; }
    else if (i < NSC0 + NSC1)            { e = 1; li = i - NSC0; }
    else if (i < NSC0 + NSC1 + NSC2)     { e = 2; li = i - NSC0 - NSC1; }
    else if (i < NSCTOT)                 { e = 3; li = i - NSC0 - NSC1 - NSC2; }
    else return;
    g_off[e][li] += g_bsum[e][li / SCAN_ITEMS];
}

__global__ void scatter4_kernel(
    const int* __restrict__ d0, const int* __restrict__ s0,
    const int* __restrict__ d1, const int* __restrict__ s1,
    const int* __restrict__ d2, const int* __restrict__ s2,
    const int* __restrict__ d3, const int* __restrict__ s3)
{
    int i = blockIdx.x * blockDim.x + threadIdx.x;
    int e; int li;
    const int* dst; const int* src; int base;
    if (i < EMT)                { e = 0; li = i;                 dst = d0; src = s0; base = 0; }
    else if (i < 2 * EMT)       { e = 1; li = i - EMT;           dst = d1; src = s1; base = EMT; }
    else if (i < 2 * EMT + EST) { e = 2; li = i - 2 * EMT;       dst = d2; src = s2; base = 2 * EMT; }
    else if (i < ETOT)          { e = 3; li = i - 2 * EMT - EST; dst = d3; src = s3; base = 2 * EMT + EST; }
    else return;
    int pos = atomicAdd(&g_fill[e][dst[li]], 1);
    g_ssrc[base + pos] = src[li];
}

// ================= GEMM body (shared by proj/lin variants) =================
#define GEMM_BODY(XA, XB, NROWS)                                               \
    int t = threadIdx.x;                                                       \
    for (int i = t; i < 4096; i += 256) {                                      \
        int k = i >> 6, c = i & 63; sWt[c * 68 + k] = W[i];                    \
    }                                                                          \
    __syncthreads();                                                           \
    int lane = t & 31, slot = t >> 5;                                          \
    long r0 = rblk + slot * 8;                                                 \
    float w0 = 1.f, w1 = 0.f;                                                  \
    if (XB) { w0 = g_w[0]; w1 = g_w[1]; }                                      \
    for (int j = lane; j < 128; j += 32) {                                     \
        int r = j >> 4, kk = (j & 15) * 4;                                     \
        float4 vv = make_float4(0.f, 0.f, 0.f, 0.f);                           \
        if (r0 + r < NROWS) {                                                  \
            vv = *(const float4*)(XA + (r0 + r) * 64 + kk);                    \
            if (XB) {                                                          \
                float4 vb = *(const float4*)(XB + (r0 + r) * 64 + kk);         \
                vv.x = w0 * vv.x + w1 * vb.x;                                  \
                vv.y = w0 * vv.y + w1 * vb.y;                                  \
                vv.z = w0 * vv.z + w1 * vb.z;                                  \
                vv.w = w0 * vv.w + w1 * vb.w;                                  \
            }                                                                  \
        }                                                                      \
        *(float4*)&sX[slot][r * 64 + kk] = vv;                                 \
    }                                                                          \
    __syncwarp();                                                              \
    float b0 = bias[lane], b1 = bias[lane + 32];                               \
    float acc0[8], acc1[8];                                                    \
    _Pragma("unroll")                                                          \
    for (int r = 0; r < 8; r++) { acc0[r] = b0; acc1[r] = b1; }                \
    _Pragma("unroll")                                                          \
    for (int k = 0; k < 64; k += 4) {                                          \
        float4 wv0 = *(const float4*)&sWt[lane * 68 + k];                      \
        float4 wv1 = *(const float4*)&sWt[(lane + 32) * 68 + k];               \
        _Pragma("unroll")                                                      \
        for (int r = 0; r < 8; r++) {                                          \
            float4 xv = *(const float4*)&sX[slot][r * 64 + k];                 \
            acc0[r] += xv.x * wv0.x + xv.y * wv0.y + xv.z * wv0.z + xv.w * wv0.w; \
            acc1[r] += xv.x * wv1.x + xv.y * wv1.y + xv.z * wv1.z + xv.w * wv1.w; \
        }                                                                      \
    }

#define ATT_DOTS(NROWS)                                                        \
    _Pragma("unroll")                                                          \
    for (int v = 0; v < 2; v++) {                                              \
        float a0v = sAv[v * 64 + lane], a1v = sAv[v * 64 + lane + 32];         \
        _Pragma("unroll")                                                      \
        for (int r = 0; r < 8; r++) {                                          \
            float p0 = acc0[r] * a0v;                                          \
            float p1 = acc1[r] * a1v;                                          \
            _Pragma("unroll")                                                  \
            for (int off = 16; off; off >>= 1) {                               \
                p0 += __shfl_xor_sync(0xffffffffu, p0, off);                   \
                p1 += __shfl_xor_sync(0xffffffffu, p1, off);                   \
            }                                                                  \
            if (lane == 0 && r0 + r < NROWS) {                                 \
                aop[v][(r0 + r) * 2]     = p0;                                 \
                aop[v][(r0 + r) * 2 + 1] = p1;                                 \
            }                                                                  \
        }                                                                      \
    }

// ---------------- member+skill projection ----------------
__global__ __launch_bounds__(256) void proj_ms_kernel(
    const float* __restrict__ xm, const float* __restrict__ xs,
    const float* __restrict__ Wb, const float* __restrict__ bb,
    const float* __restrict__ aSb, const float* __restrict__ aDb)
{
    __shared__ float sWt[64 * 68];
    __shared__ float sAv[2 * 64];
    __shared__ float sX[8][512];

    int b = blockIdx.x;
    int N; long rblk;
    const float* xA;
    float* hout;
    const float* avp[2];
    float* aop[2];
    const float* W; const float* bias;

    if (b < BM) {
        N = NM; rblk = (long)b * 64; xA = xm; hout = g_h0;
        avp[0] = aSb + 0;   aop[0] = &g_as[0][0];
        avp[1] = aDb + 64;  aop[1] = &g_ad[1][0];
        W = Wb; bias = bb;
    } else {
        N = NS; rblk = (long)(b - BM) * 64; xA = xs; hout = g_h1;
        avp[0] = aSb + 128; aop[0] = &g_as[2][0];
        avp[1] = aDb + 192; aop[1] = &g_ad[3][0];
        W = Wb + 4096; bias = bb + 64;
    }
    if (threadIdx.x < 64) {
        sAv[threadIdx.x] = avp[0][threadIdx.x];
        sAv[64 + threadIdx.x] = avp[1][threadIdx.x];
    }

    const float* xB = nullptr;
    GEMM_BODY(xA, xB, N)

    #pragma unroll
    for (int r = 0; r < 8; r++) {
        if (r0 + r < N) {
            hout[(r0 + r) * 64 + lane]      = acc0[r];
            hout[(r0 + r) * 64 + lane + 32] = acc1[r];
        }
    }
    ATT_DOTS(N)
}

// ---------------- team projection (with semantic blend) ----------------
__global__ __launch_bounds__(256) void proj_t_kernel(
    const float* __restrict__ xtA, const float* __restrict__ xtB,
    const float* __restrict__ Wb, const float* __restrict__ bb,
    const float* __restrict__ aSb, const float* __restrict__ aDb)
{
    __shared__ float sWt[64 * 68];
    __shared__ float sAv[4 * 64];
    __shared__ float sX[8][512];

    long rblk = (long)blockIdx.x * 64;
    const float* W = Wb + 2 * 4096;
    const float* bias = bb + 2 * 64;
    const float* avp[4] = {aSb + 64, aSb + 192, aDb + 0, aDb + 128};
    float* aop[4] = {&g_as[1][0], &g_as[3][0], &g_ad[0][0], &g_ad[2][0]};
    if (threadIdx.x < 64) {
        #pragma unroll
        for (int v = 0; v < 4; v++) sAv[v * 64 + threadIdx.x] = avp[v][threadIdx.x];
    }

    GEMM_BODY(xtA, xtB, NT)

    #pragma unroll
    for (int r = 0; r < 8; r++) {
        if (r0 + r < NT) {
            g_h2[(r0 + r) * 64 + lane]      = acc0[r];
            g_h2[(r0 + r) * 64 + lane + 32] = acc1[r];
        }
    }

    #pragma unroll
    for (int v = 0; v < 4; v++) {
        float a0v = sAv[v * 64 + lane], a1v = sAv[v * 64 + lane + 32];
        #pragma unroll
        for (int r = 0; r < 8; r++) {
            float p0 = acc0[r] * a0v;
            float p1 = acc1[r] * a1v;
            #pragma unroll
            for (int off = 16; off; off >>= 1) {
                p0 += __shfl_xor_sync(0xffffffffu, p0, off);
                p1 += __shfl_xor_sync(0xffffffffu, p1, off);
            }
            if (lane == 0 && r0 + r < NT) {
                aop[v][(r0 + r) * 2]     = p0;
                aop[v][(r0 + r) * 2 + 1] = p1;
            }
        }
    }
}

// ---------------- gather segment kernel: quarter-warp per destination ----------------
// One warp serves 4 dst nodes (8 lanes each). Lane li8 = lane&7 owns cols
// [li8*8, li8*8+8) as two float4s. Head = li8>>2. Per inner iteration the warp
// covers 4 edges with 3 SHFL + 2 LDG + 8 FFMA -> fewer warp-instructions/edge.
// Segment layout (warp units): [0,WG0): e0 | [WG0,WGT): e2 |
//   [WGT, WGT+WG1): e1 | [WGT+WG1, WGT+WGMS): e3
__global__ __launch_bounds__(256) void gather_seg_kernel(long gwbase)
{
    long gw = gwbase + (((long)blockIdx.x * blockDim.x + threadIdx.x) >> 5);
    int lane = threadIdx.x & 31;
    int li8 = lane & 7;
    int grp = lane >> 3;           // 0..3
    int gb = grp << 3;             // group base lane

    int e; long lw;
    if (gw < WG0)                 { e = 0; lw = gw; }
    else if (gw < WGT)            { e = 2; lw = gw - WG0; }
    else if (gw < WGT + WG1)      { e = 1; lw = gw - WGT; }
    else if (gw < WGT + WGMS)     { e = 3; lw = gw - WGT - WG1; }
    else return;

    const float* h;
    float* outp;
    const int* ssrc;
    int N;
    if (e == 0)      { h = g_h0; outp = g_oT0; ssrc = g_ssrc;                 N = NT; }
    else if (e == 1) { h = g_h2; outp = g_o0;  ssrc = g_ssrc + EMT;           N = NM; }
    else if (e == 2) { h = g_h1; outp = g_oT1; ssrc = g_ssrc + 2 * EMT;       N = NT; }
    else             { h = g_h2; outp = g_o1;  ssrc = g_ssrc + 2 * EMT + EST; N = NS; }
    const float* as = &g_as[e][0];
    const float* ad = &g_ad[e][0];
    const int* off = &g_off[e][0];

    long d = lw * 4 + grp;
    bool act = d < N;
    int beg = 0, end = 0;
    if (act) { beg = off[d]; end = off[d + 1]; }
    int head = li8 >> 2;           // cols [li8*8, li8*8+8) all in head li8>>2
    int c0 = li8 * 8;

    float ad0 = 0.f, ad1 = 0.f;
    if (act) { float2 tt = *(const float2*)(ad + d * 2); ad0 = tt.x; ad1 = tt.y; }

    float4 accL = make_float4(0.f, 0.f, 0.f, 0.f);
    float4 accH = make_float4(0.f, 0.f, 0.f, 0.f);
    float se0 = 0.f, se1 = 0.f;

    int trips = (end - beg + 7) >> 3;
    trips = max(trips, __shfl_xor_sync(0xffffffffu, trips, 8));
    trips = max(trips, __shfl_xor_sync(0xffffffffu, trips, 16));

    for (int k = 0; k < trips; k++) {
        int base = beg + (k << 3);
        int idx = base + li8;
        int s = 0;
        float ex0 = 0.f, ex1 = 0.f;
        if (act && idx < end) {
            s = ssrc[idx];
            float2 av = *(const float2*)(as + (long)s * 2);
            float l0 = av.x + ad0; l0 = (l0 >= 0.f) ? l0 : 0.2f * l0;
            float l1 = av.y + ad1; l1 = (l1 >= 0.f) ? l1 : 0.2f * l1;
            ex0 = __expf(l0); ex1 = __expf(l1);
            se0 += ex0; se1 += ex1;
        }
        int cnt = end - base;
        cnt = (cnt < 0) ? 0 : ((cnt > 8) ? 8 : cnt);
        int cm = max(cnt, __shfl_xor_sync(0xffffffffu, cnt, 8));
        cm = max(cm, __shfl_xor_sync(0xffffffffu, cm, 16));
        for (int i = 0; i < cm; i++) {
            int sl = gb + i;
            int si   = __shfl_sync(0xffffffffu, s,   sl);
            float e0 = __shfl_sync(0xffffffffu, ex0, sl);
            float e1 = __shfl_sync(0xffffffffu, ex1, sl);
            float ee = head ? e1 : e0;
            const float* row = h + (long)si * 64 + c0;
            float4 vL = *(const float4*)row;
            float4 vH = *(const float4*)(row + 4);
            accL.x += ee * vL.x; accL.y += ee * vL.y;
            accL.z += ee * vL.z; accL.w += ee * vL.w;
            accH.x += ee * vH.x; accH.y += ee * vH.y;
            accH.z += ee * vH.z; accH.w += ee * vH.w;
        }
    }

    // reduce softmax denominators within each 8-lane group
    #pragma unroll
    for (int o = 4; o; o >>= 1) {
        se0 += __shfl_xor_sync(0xffffffffu, se0, o);
        se1 += __shfl_xor_sync(0xffffffffu, se1, o);
    }
    if (act) {
        float inv = 1.0f / ((head ? se1 : se0) + 1e-16f);
        accL.x = fmaxf(accL.x * inv, 0.f);
        accL.y = fmaxf(accL.y * inv, 0.f);
        accL.z = fmaxf(accL.z * inv, 0.f);
        accL.w = fmaxf(accL.w * inv, 0.f);
        accH.x = fmaxf(accH.x * inv, 0.f);
        accH.y = fmaxf(accH.y * inv, 0.f);
        accH.z = fmaxf(accH.z * inv, 0.f);
        accH.w = fmaxf(accH.w * inv, 0.f);
        float* orow = outp + d * 64 + c0;
        *(float4*)orow = accL;
        *(float4*)(orow + 4) = accH;
    }
}

// ---------------- merged semantic GEMM reduction ----------------
__global__ __launch_bounds__(256) void sem2_kernel(
    const float* __restrict__ W, const float* __restrict__ bias)
{
    __shared__ float sWt[64 * 68];
    __shared__ float sX[8][512];
    __shared__ float sAcc[64];

    int b = blockIdx.x;
    const float* xA = (b < BT) ? g_oT0 : g_oT1;
    float* acc_out = (b < BT) ? g_acc : (g_acc + 64);
    long rblk = (long)((b < BT) ? b : (b - BT)) * 64;
    if (threadIdx.x < 64) sAcc[threadIdx.x] = 0.f;

    const float* xB = nullptr;
    GEMM_BODY(xA, xB, NT)

    float s0 = 0.f, s1 = 0.f;
    #pragma unroll
    for (int r = 0; r < 8; r++) {
        if (r0 + r < NT) { s0 += fast_tanh(acc0[r]); s1 += fast_tanh(acc1[r]); }
    }
    atomicAdd(&sAcc[lane], s0);
    atomicAdd(&sAcc[lane + 32], s1);
    __syncthreads();
    if (t < 64) atomicAdd(&acc_out[t], sAcc[t]);
}

// ---------------- semantic finalize (re-zeros acc) ----------------
__global__ void sem_finalize_kernel(const float* __restrict__ q)
{
    __shared__ float s0[64], s1[64];
    int t = threadIdx.x;
    s0[t] = q[t] * g_acc[t]      * (1.0f / NT);
    s1[t] = q[t] * g_acc[64 + t] * (1.0f / NT);
    __syncthreads();
    g_acc[t] = 0.f;
    g_acc[64 + t] = 0.f;
    if (t == 0) {
        float a = 0.f, b = 0.f;
        for (int i = 0; i < 64; i++) { a += s0[i]; b += s1[i]; }
        float m = fmaxf(a, b);
        float e0 = __expf(a - m), e1 = __expf(b - m);
        float inv = 1.0f / (e0 + e1);
        g_w[0] = e0 * inv;
        g_w[1] = e1 * inv;
    }
}

// ---------------- final linear: member+skill ----------------
__global__ __launch_bounds__(256) void lin_ms_kernel(
    const float* __restrict__ W, const float* __restrict__ bias, float* __restrict__ out)
{
    __shared__ float sWt[64 * 68];
    __shared__ float sX[8][512];

    int b = blockIdx.x;
    int N; long rblk;
    const float* xA;
    float* op;
    if (b < BM) { N = NM; rblk = (long)b * 64; xA = g_o0; op = out; }
    else        { N = NS; rblk = (long)(b - BM) * 64; xA = g_o1; op = out + (long)NM * 64; }

    const float* xB = nullptr;
    GEMM_BODY(xA, xB, N)

    #pragma unroll
    for (int r = 0; r < 8; r++) {
        if (r0 + r < N) {
            op[(r0 + r) * 64 + lane]      = acc0[r];
            op[(r0 + r) * 64 + lane + 32] = acc1[r];
        }
    }
}

// ---------------- final linear: team (with blend) ----------------
__global__ __launch_bounds__(256) void lin_t_kernel(
    const float* __restrict__ W, const float* __restrict__ bias, float* __restrict__ out)
{
    __shared__ float sWt[64 * 68];
    __shared__ float sX[8][512];

    long rblk = (long)blockIdx.x * 64;
    float* op = out + (long)(NM + NS) * 64;

    GEMM_BODY(g_oT0, g_oT1, NT)

    #pragma unroll
    for (int r = 0; r < 8; r++) {
        if (r0 + r < NT) {
            op[(r0 + r) * 64 + lane]      = acc0[r];
            op[(r0 + r) * 64 + lane + 32] = acc1[r];
        }
    }
}

// ---------------- host orchestration ----------------
extern "C" void kernel_launch(void* const* d_in, const int* in_sizes, int n_in,
                              void* d_out, int out_size)
{
    (void)in_sizes; (void)n_in; (void)out_size;
    const float* x_m  = (const float*)d_in[0];
    const float* x_s  = (const float*)d_in[1];
    const float* x_t  = (const float*)d_in[2];
    const int* src_mt = (const int*)d_in[3];
    const int* dst_mt = (const int*)d_in[4];
    const int* src_tm = (const int*)d_in[5];
    const int* dst_tm = (const int*)d_in[6];
    const int* src_st = (const int*)d_in[7];
    const int* dst_st = (const int*)d_in[8];
    const int* src_ts = (const int*)d_in[9];
    const int* dst_ts = (const int*)d_in[10];
    const float* Wp   = (const float*)d_in[11];
    const float* bp   = (const float*)d_in[12];
    const float* aS   = (const float*)d_in[13];
    const float* aD   = (const float*)d_in[14];
    const float* kWp  = (const float*)d_in[15];
    const float* kbp  = (const float*)d_in[16];
    const float* qp   = (const float*)d_in[17];
    const float* linW = (const float*)d_in[18];
    const float* linb = (const float*)d_in[19];
    float* out = (float*)d_out;

    float *o0, *o1, *oT0, *oT1, *accp;
    int *cntb, *offb, *fillb;
    cudaGetSymbolAddress((void**)&o0,  g_o0);
    cudaGetSymbolAddress((void**)&o1,  g_o1);
    cudaGetSymbolAddress((void**)&oT0, g_oT0);
    cudaGetSymbolAddress((void**)&oT1, g_oT1);
    cudaGetSymbolAddress((void**)&accp, g_acc);
    cudaGetSymbolAddress((void**)&cntb, g_cnt);
    cudaGetSymbolAddress((void**)&offb, g_off);
    cudaGetSymbolAddress((void**)&fillb, g_fill);

    static cudaStream_t s_side = nullptr;
    static cudaEvent_t s_fork = nullptr, s_join = nullptr, s_evG = nullptr, s_evS = nullptr;
    if (!s_side) {
        cudaStreamCreateWithFlags(&s_side, cudaStreamNonBlocking);
        cudaEventCreateWithFlags(&s_fork, cudaEventDisableTiming);
        cudaEventCreateWithFlags(&s_join, cudaEventDisableTiming);
        cudaEventCreateWithFlags(&s_evG, cudaEventDisableTiming);
        cudaEventCreateWithFlags(&s_evS, cudaEventDisableTiming);
    }

    // ---- fork: CSR build on side stream, overlapped with layer-0 projection ----
    cudaEventRecord(s_fork, 0);
    cudaStreamWaitEvent(s_side, s_fork, 0);

    cudaMemsetAsync(cntb, 0, sizeof(int) * 4 * (MAXN + 1), s_side);
    hist4_kernel<<<(ETOT + 255) / 256, 256, 0, s_side>>>(dst_mt, dst_tm, dst_st, dst_ts);
    scan1m_kernel<<<NBTOT, SCAN_BLOCK, 0, s_side>>>();
    scan2m_kernel<<<4, 128, 0, s_side>>>();
    scan3m_kernel<<<(NSCTOT + 255) / 256, 256, 0, s_side>>>();
    cudaMemcpyAsync(fillb, offb, sizeof(int) * 4 * (MAXN + 1),
                    cudaMemcpyDeviceToDevice, s_side);
    scatter4_kernel<<<(ETOT + 255) / 256, 256, 0, s_side>>>(
        dst_mt, src_mt, dst_tm, src_tm, dst_st, src_st, dst_ts, src_ts);
    cudaMemsetAsync(accp, 0, 128 * sizeof(float), s_side);
    cudaEventRecord(s_join, s_side);

    // layer-0 projection on main (no CSR, no g_w dependency)
    proj_ms_kernel<<<BM + BS, 256>>>(x_m, x_s, Wp, bp, aS, aD);
    proj_t_kernel<<<BT, 256>>>(x_t, nullptr, Wp, bp, aS, aD);

    cudaStreamWaitEvent(0, s_join, 0);

    for (int l = 0; l < 3; l++) {
        // team-destination gather first (produces oT0/oT1 for sem2)
        gather_seg_kernel<<<GT_BLOCKS, 256>>>(0);

        // fork: sem2 + finalize on side stream as soon as team gather is done
        cudaEventRecord(s_evG, 0);
        cudaStreamWaitEvent(s_side, s_evG, 0);
        sem2_kernel<<<2 * BT, 256, 0, s_side>>>(kWp + (long)l * 4096, kbp + (long)l * 64);
        sem_finalize_kernel<<<1, 64, 0, s_side>>>(qp + (long)l * 64);
        cudaEventRecord(s_evS, s_side);

        // member/skill-destination gather on main (independent of sem2)
        gather_seg_kernel<<<GMS_BLOCKS, 256>>>(WGT);

        // member/skill GEMM work on main (independent of g_w)
        if (l < 2) {
            proj_ms_kernel<<<BM + BS, 256>>>(o0, o1,
                Wp + (long)(l + 1) * 3 * 4096, bp + (long)(l + 1) * 3 * 64,
                aS + (long)(l + 1) * 4 * 64, aD + (long)(l + 1) * 4 * 64);
        } else {
            lin_ms_kernel<<<BM + BS, 256>>>(linW, linb, out);
        }

        // join, then team work (needs g_w)
        cudaStreamWaitEvent(0, s_evS, 0);
        if (l < 2) {
            proj_t_kernel<<<BT, 256>>>(oT0, oT1,
                Wp + (long)(l + 1) * 3 * 4096, bp + (long)(l + 1) * 3 * 64,
                aS + (long)(l + 1) * 4 * 64, aD + (long)(l + 1) * 4 * 64);
        } else {
            lin_t_kernel<<<BT, 256>>>(linW, linb, out);
        }
    }
}